// round 5
// baseline (speedup 1.0000x reference)
#include <cuda_runtime.h>
#include <math.h>

#define BB 32
#define LL 2048
#define HH 8
#define DMET 16
#define SDIM 27
#define DM 256
#define NLAYERS 4
#define DS 64
#define TE 256
#define LT 2055          // LL + HH - 1
#define LTP 2056         // padded row stride
#define FIN 44           // DMET + 1 + SDIM
#define NT 544           // 17 l-tiles * 32 batches (BN partial slots)

typedef unsigned long long ull;

// ---------------- scratch (device globals; no allocation) ----------------
__device__ float g_h[(size_t)BB * DM * LTP];   // activations (pre-BN) [b][d][l]
__device__ float g_y[(size_t)BB * DM * LTP];   // gelu(ssm out)        [b][d][l]
__device__ float g_tb[BB * DM];
__device__ float g_mean[DM], g_rstd[DM];
__device__ float g_bnp0[DM * NT], g_bnp1[DM * NT];

// ---------------- f32x2 packed math ----------------
__device__ __forceinline__ ull pk2(float a, float b) {
    ull r; asm("mov.b64 %0,{%1,%2};" : "=l"(r) : "f"(a), "f"(b)); return r;
}
__device__ __forceinline__ void up2(ull v, float& a, float& b) {
    asm("mov.b64 {%0,%1},%2;" : "=f"(a), "=f"(b) : "l"(v));
}
__device__ __forceinline__ ull f2fma(ull a, ull b, ull c) {
    ull d; asm("fma.rn.f32x2 %0,%1,%2,%3;" : "=l"(d) : "l"(a), "l"(b), "l"(c)); return d;
}
__device__ __forceinline__ ull f2mul(ull a, ull b) {
    ull d; asm("mul.rn.f32x2 %0,%1,%2;" : "=l"(d) : "l"(a), "l"(b)); return d;
}

// ---------------- helpers ----------------
__device__ __forceinline__ float sigm(float x) { return 1.f / (1.f + __expf(-x)); }
__device__ __forceinline__ float gelu_tanh(float v) {
    float v3 = v * v * v;
    float w = 1.5957691216057308f * fmaf(0.044715f, v3, v);
    return v * sigm(w);
}

// ---------------- time MLP ----------------
__global__ void k_timemlp(const float* __restrict__ t, const float* __restrict__ freqs,
                          const float* __restrict__ phases,
                          const float* __restrict__ W1, const float* __restrict__ b1,
                          const float* __restrict__ W2, const float* __restrict__ b2) {
    int b = blockIdx.x, tid = threadIdx.x;
    __shared__ float tf[TE];
    __shared__ float hid[2 * TE];
    float tv = t[b];
    tf[tid] = cosf(fmaf(tv, freqs[tid], phases[tid])) * 1.41421356237309515f;
    __syncthreads();
    for (int j = tid; j < 2 * TE; j += 256) {
        float acc = b1[j];
        #pragma unroll 8
        for (int k = 0; k < TE; ++k) acc = fmaf(tf[k], W1[k * 512 + j], acc);
        hid[j] = acc * sigm(acc);
    }
    __syncthreads();
    float acc = b2[tid];
    #pragma unroll 8
    for (int k = 0; k < 2 * TE; ++k) acc = fmaf(hid[k], W2[k * 256 + tid], acc);
    g_tb[b * DM + tid] = acc;
}

// ---------------- input projection ----------------
__global__ void k_inproj(const float* __restrict__ xp, const float* __restrict__ noisy,
                         const float* __restrict__ xf, const float* __restrict__ sa,
                         const float* __restrict__ inW, const float* __restrict__ inb) {
    int b = blockIdx.z, dt = blockIdx.y, ltile = blockIdx.x;
    int tid = threadIdx.x;
    int ll = tid & 31, dl = tid >> 5;
    int l0 = ltile * 32, d0 = dt * 8;
    __shared__ float sf[32][45];
    __shared__ float sw[FIN][8];
    for (int i = tid; i < 32 * FIN; i += 256) {
        int li = i / FIN, f = i % FIN;
        int l = l0 + li;
        float v = 0.f;
        if (l < LT) {
            if (f < DMET)
                v = (l < LL) ? xp[((size_t)b * LL + l) * DMET + f]
                             : xf[((size_t)b * (HH - 1) + (l - LL)) * DMET + f];
            else if (f == DMET)
                v = (l >= LL - 1) ? noisy[b * HH + (l - (LL - 1))] : 0.f;
            else
                v = sa[b * SDIM + (f - DMET - 1)];
        }
        sf[li][f] = v;
    }
    for (int i = tid; i < FIN * 8; i += 256) {
        int f = i >> 3, c = i & 7;
        sw[f][c] = inW[f * DM + d0 + c];
    }
    __syncthreads();
    int l = l0 + ll, d = d0 + dl;
    float acc = inb[d];
    #pragma unroll
    for (int f = 0; f < FIN; ++f) acc = fmaf(sf[ll][f], sw[f][dl], acc);
    if (l >= LL - 1) acc += g_tb[b * DM + d];
    if (l < LT) g_h[((size_t)b * DM + d) * LTP + l] = acc;
}

// ---- SSM scan: warp per (b,d), inline discretization, f32x2, smem transpose --------
__global__ void __launch_bounds__(256) k_scan(const float* __restrict__ log_dt,
                                              const float* __restrict__ Are,
                                              const float* __restrict__ Aim,
                                              const float* __restrict__ Cre,
                                              const float* __restrict__ Cim,
                                              const float* __restrict__ Dv,
                                              const float* __restrict__ pg,
                                              const float* __restrict__ pb,
                                              int apply_bn) {
    __shared__ float sp[8][32][33];
    int warp = threadIdx.x >> 5, lane = threadIdx.x & 31;
    int wid = blockIdx.x * 8 + warp;
    int b = wid >> 8, d = wid & 255;
    float mean = 0.f, scl = 1.f, bet = 0.f;
    if (apply_bn) { mean = g_mean[d]; scl = g_rstd[d] * pg[d]; bet = pb[d]; }
    // inline discretization for this lane's two states
    float dt = expf(log_dt[d]);
    float a0r, a0i, c0kr, c0ki, a1r, a1i, c1kr, c1ki;
    {
        int i0 = d * DS + lane, i1 = i0 + 32;
        #pragma unroll
        for (int s = 0; s < 2; ++s) {
            int ii = s ? i1 : i0;
            float ar_ = Are[ii], ai_ = Aim[ii];
            float xr = dt * ar_, xi = dt * ai_;
            float mag = expf(xr);
            float cs = cosf(xi), sn = sinf(xi);
            float A_r = mag * cs, A_i = mag * sn;
            float em = expm1f(xr);
            float er = fmaf(em, cs, cs - 1.f);
            float ei = A_i;
            float inv = 1.f / fmaf(ar_, ar_, ai_ * ai_);
            float qr = fmaf(er, ar_, ei * ai_) * inv;
            float qi = fmaf(ei, ar_, -er * ai_) * inv;
            float cr = Cre[ii], ci = Cim[ii];
            float kr = 2.f * fmaf(cr, qr, -ci * qi);
            float ki = 2.f * fmaf(cr, qi, ci * qr);
            if (s == 0) { a0r = A_r; a0i = A_i; c0kr = kr; c0ki = ki; }
            else        { a1r = A_r; a1i = A_i; c1kr = kr; c1ki = ki; }
        }
    }
    ull ar2  = pk2(a0r, a1r);
    ull ai2  = pk2(a0i, a1i);
    ull nai2 = pk2(-a0i, -a1i);
    ull cr2  = pk2(c0kr, c1kr);
    ull nci2 = pk2(-c0ki, -c1ki);
    ull sr2 = 0ull, si2 = 0ull;
    float Dd = Dv[d];
    const float* u = g_h + ((size_t)b * DM + d) * LTP;
    float* yo = g_y + ((size_t)b * DM + d) * LTP;

    for (int l0 = 0; l0 < 2048; l0 += 32) {
        float rv = u[l0 + lane];
        rv = fmaf(rv - mean, scl, bet);
        #pragma unroll
        for (int j = 0; j < 32; ++j) {
            float uv = __shfl_sync(0xffffffffu, rv, j);
            ull uv2 = pk2(uv, uv);
            ull t   = f2fma(nai2, si2, uv2);
            ull nsr = f2fma(ar2, sr2, t);
            ull nsi = f2fma(ai2, sr2, f2mul(ar2, si2));
            sr2 = nsr; si2 = nsi;
            ull pr = f2fma(cr2, sr2, f2mul(nci2, si2));
            float px, py; up2(pr, px, py);
            sp[warp][j][lane] = px + py;   // [step][owner]
        }
        __syncwarp();
        // output position = lane: sum 32 owners with 4 interleaved accumulators
        float c0 = 0.f, c1 = 0.f, c2 = 0.f, c3 = 0.f;
        #pragma unroll
        for (int j = 0; j < 32; j += 4) {
            c0 += sp[warp][lane][j];
            c1 += sp[warp][lane][j + 1];
            c2 += sp[warp][lane][j + 2];
            c3 += sp[warp][lane][j + 3];
        }
        float cs = (c0 + c1) + (c2 + c3);
        yo[l0 + lane] = gelu_tanh(fmaf(Dd, rv, cs));
        __syncwarp();
    }
    // tail: 7 steps
    {
        const int l0 = 2048;
        float rv = (lane < 7) ? fmaf(u[l0 + lane] - mean, scl, bet) : 0.f;
        #pragma unroll
        for (int j = 0; j < 7; ++j) {
            float uv = __shfl_sync(0xffffffffu, rv, j);
            ull uv2 = pk2(uv, uv);
            ull t   = f2fma(nai2, si2, uv2);
            ull nsr = f2fma(ar2, sr2, t);
            ull nsi = f2fma(ai2, sr2, f2mul(ar2, si2));
            sr2 = nsr; si2 = nsi;
            ull pr = f2fma(cr2, sr2, f2mul(nci2, si2));
            float px, py; up2(pr, px, py);
            sp[warp][j][lane] = px + py;
        }
        __syncwarp();
        if (lane < 7) {
            float cs = 0.f;
            #pragma unroll
            for (int j = 0; j < 32; ++j) cs += sp[warp][lane][j];
            yo[l0 + lane] = gelu_tanh(fmaf(Dd, rv, cs));
        }
    }
}

// ---- out-proj GEMM: 64d x 128l tile, dup'd-A f32x2, double-buffered, 1 sync/kt ------
__global__ void __launch_bounds__(256) k_gemm(const float* __restrict__ W,
                                              const float* __restrict__ ob,
                                              const float* __restrict__ pg,
                                              const float* __restrict__ pb,
                                              int apply_bn) {
    const int b = blockIdx.z, dt = blockIdx.y, lt = blockIdx.x;
    const int tid = threadIdx.x;
    const int lr = tid & 15, dr = tid >> 4;      // lr: 8-l group, dr: 4-d group
    const int d0 = dt * 64, l0 = lt * 128;
    __shared__ float As1[2][16][128];   // dup'd pairs (d,d)
    __shared__ float As2[2][16][128];
    __shared__ float Bs[2][16][128];
    ull ac1[4][4], ac2[4][4];
    #pragma unroll
    for (int j = 0; j < 4; ++j)
        #pragma unroll
        for (int m = 0; m < 4; ++m) { ac1[j][m] = 0ull; ac2[j][m] = 0ull; }

    const float* Yb = g_y + (size_t)b * DM * LTP;
    const int lf = tid >> 4;            // load row (0..15)
    const int la = (tid & 15) * 4;      // A col (in d units)
    const int lb = (tid & 15) * 8;      // B col

    float4 pA1, pA2, pB0, pB1;
    // load kt = 0
    {
        const float* wr = W + lf * 512 + d0;
        pA1 = *(const float4*)(wr + la);
        pA2 = *(const float4*)(wr + 256 + la);
        const float* yr = Yb + (size_t)lf * LTP + l0 + lb;
        if (l0 + lb + 7 < LT) {
            pB0 = *(const float4*)yr;
            pB1 = *(const float4*)(yr + 4);
        } else {
            float v[8];
            #pragma unroll
            for (int e = 0; e < 8; ++e) v[e] = (l0 + lb + e < LT) ? yr[e] : 0.f;
            pB0 = make_float4(v[0], v[1], v[2], v[3]);
            pB1 = make_float4(v[4], v[5], v[6], v[7]);
        }
    }
    // store stage 0 (A dup'd)
    {
        float* a1w = &As1[0][lf][la * 2];
        a1w[0] = pA1.x; a1w[1] = pA1.x; a1w[2] = pA1.y; a1w[3] = pA1.y;
        a1w[4] = pA1.z; a1w[5] = pA1.z; a1w[6] = pA1.w; a1w[7] = pA1.w;
        float* a2w = &As2[0][lf][la * 2];
        a2w[0] = pA2.x; a2w[1] = pA2.x; a2w[2] = pA2.y; a2w[3] = pA2.y;
        a2w[4] = pA2.z; a2w[5] = pA2.z; a2w[6] = pA2.w; a2w[7] = pA2.w;
        *(float4*)&Bs[0][lf][lb]     = pB0;
        *(float4*)&Bs[0][lf][lb + 4] = pB1;
    }
    __syncthreads();

    for (int kt = 0; kt < 16; ++kt) {
        const int s = kt & 1;
        if (kt < 15) {
            int k0 = (kt + 1) * 16;
            const float* wr = W + (k0 + lf) * 512 + d0;
            pA1 = *(const float4*)(wr + la);
            pA2 = *(const float4*)(wr + 256 + la);
            const float* yr = Yb + (size_t)(k0 + lf) * LTP + l0 + lb;
            if (l0 + lb + 7 < LT) {
                pB0 = *(const float4*)yr;
                pB1 = *(const float4*)(yr + 4);
            } else {
                float v[8];
                #pragma unroll
                for (int e = 0; e < 8; ++e) v[e] = (l0 + lb + e < LT) ? yr[e] : 0.f;
                pB0 = make_float4(v[0], v[1], v[2], v[3]);
                pB1 = make_float4(v[4], v[5], v[6], v[7]);
            }
        }
        #pragma unroll
        for (int kk = 0; kk < 16; ++kk) {
            ulonglong2 qa1 = *(const ulonglong2*)&As1[s][kk][dr * 8];      // (d0,d0),(d1,d1)
            ulonglong2 qb1 = *(const ulonglong2*)&As1[s][kk][dr * 8 + 4];  // (d2,d2),(d3,d3)
            ulonglong2 qa2 = *(const ulonglong2*)&As2[s][kk][dr * 8];
            ulonglong2 qb2 = *(const ulonglong2*)&As2[s][kk][dr * 8 + 4];
            ulonglong2 b01 = *(const ulonglong2*)&Bs[s][kk][lr * 8];
            ulonglong2 b23 = *(const ulonglong2*)&Bs[s][kk][lr * 8 + 4];
            ull bp[4]  = { b01.x, b01.y, b23.x, b23.y };
            ull a1d[4] = { qa1.x, qa1.y, qb1.x, qb1.y };
            ull a2d[4] = { qa2.x, qa2.y, qb2.x, qb2.y };
            #pragma unroll
            for (int j = 0; j < 4; ++j)
                #pragma unroll
                for (int m = 0; m < 4; ++m) {
                    ac1[j][m] = f2fma(a1d[j], bp[m], ac1[j][m]);
                    ac2[j][m] = f2fma(a2d[j], bp[m], ac2[j][m]);
                }
        }
        if (kt < 15) {
            const int sn = (kt + 1) & 1;
            float* a1w = &As1[sn][lf][la * 2];
            a1w[0] = pA1.x; a1w[1] = pA1.x; a1w[2] = pA1.y; a1w[3] = pA1.y;
            a1w[4] = pA1.z; a1w[5] = pA1.z; a1w[6] = pA1.w; a1w[7] = pA1.w;
            float* a2w = &As2[sn][lf][la * 2];
            a2w[0] = pA2.x; a2w[1] = pA2.x; a2w[2] = pA2.y; a2w[3] = pA2.y;
            a2w[4] = pA2.z; a2w[5] = pA2.z; a2w[6] = pA2.w; a2w[7] = pA2.w;
            *(float4*)&Bs[sn][lf][lb]     = pB0;
            *(float4*)&Bs[sn][lf][lb + 4] = pB1;
            __syncthreads();
        }
    }

    // epilogue: glu + lazy-BN residual + stats (8 contiguous l per thread per d)
    float* Hb = g_h + (size_t)b * DM * LTP;
    const int lbase = l0 + lr * 8;
    float s[4], s2[4];
    #pragma unroll
    for (int j = 0; j < 4; ++j) { s[j] = 0.f; s2[j] = 0.f; }
    #pragma unroll
    for (int j = 0; j < 4; ++j) {
        int d = d0 + dr * 4 + j;
        float bz1 = ob[d], bz2 = ob[256 + d];
        float mn = 0.f, sc = 1.f, bt = 0.f;
        if (apply_bn) { mn = g_mean[d]; sc = g_rstd[d] * pg[d]; bt = pb[d]; }
        float* hrow = Hb + (size_t)d * LTP + lbase;
        float hv[8];
        bool full = (lbase + 7 < LT);
        if (full) {
            float4 t0 = *(const float4*)hrow;
            float4 t1 = *(const float4*)(hrow + 4);
            hv[0]=t0.x; hv[1]=t0.y; hv[2]=t0.z; hv[3]=t0.w;
            hv[4]=t1.x; hv[5]=t1.y; hv[6]=t1.z; hv[7]=t1.w;
        } else {
            #pragma unroll
            for (int e = 0; e < 8; ++e) hv[e] = (lbase + e < LT) ? hrow[e] : 0.f;
        }
        float hn[8];
        #pragma unroll
        for (int m = 0; m < 4; ++m) {
            float z1a, z1b, z2a, z2b;
            up2(ac1[j][m], z1a, z1b);
            up2(ac2[j][m], z2a, z2b);
            float ga = (z1a + bz1) * sigm(z2a + bz2);
            float gb = (z1b + bz1) * sigm(z2b + bz2);
            hn[2*m]   = fmaf(hv[2*m]   - mn, sc, bt) + ga;
            hn[2*m+1] = fmaf(hv[2*m+1] - mn, sc, bt) + gb;
        }
        if (full) {
            *(float4*)hrow       = make_float4(hn[0], hn[1], hn[2], hn[3]);
            *(float4*)(hrow + 4) = make_float4(hn[4], hn[5], hn[6], hn[7]);
            #pragma unroll
            for (int e = 0; e < 8; ++e) { s[j] += hn[e]; s2[j] = fmaf(hn[e], hn[e], s2[j]); }
        } else {
            #pragma unroll
            for (int e = 0; e < 8; ++e)
                if (lbase + e < LT) {
                    hrow[e] = hn[e];
                    s[j] += hn[e]; s2[j] = fmaf(hn[e], hn[e], s2[j]);
                }
        }
    }
    #pragma unroll
    for (int o = 8; o; o >>= 1) {
        #pragma unroll
        for (int j = 0; j < 4; ++j) {
            s[j]  += __shfl_xor_sync(0xffffffffu, s[j], o);
            s2[j] += __shfl_xor_sync(0xffffffffu, s2[j], o);
        }
    }
    if (lr == 0) {
        int slot = lt * 32 + b;
        #pragma unroll
        for (int j = 0; j < 4; ++j) {
            int d = d0 + dr * 4 + j;
            g_bnp0[d * NT + slot] = s[j];
            g_bnp1[d * NT + slot] = s2[j];
        }
    }
}

// ---------------- BN finalize (reduce partials) ----------------
__global__ void k_bnfin() {
    int d = blockIdx.x, tid = threadIdx.x;   // 128 threads
    float s = 0.f, s2 = 0.f;
    for (int i = tid; i < NT; i += 128) {
        s  += g_bnp0[d * NT + i];
        s2 += g_bnp1[d * NT + i];
    }
    __shared__ float sh1[128], sh2[128];
    sh1[tid] = s; sh2[tid] = s2;
    __syncthreads();
    for (int o = 64; o; o >>= 1) {
        if (tid < o) { sh1[tid] += sh1[tid + o]; sh2[tid] += sh2[tid + o]; }
        __syncthreads();
    }
    if (tid == 0) {
        float n = (float)(BB * LT);
        float mean = sh1[0] / n;
        float var = sh2[0] / n - mean * mean;
        g_mean[d] = mean;
        g_rstd[d] = rsqrtf(var + 1e-5f);
    }
}

// ---------------- head (applies final BN lazily) ----------------
__global__ void k_head(const float* __restrict__ W1, const float* __restrict__ b1,
                       const float* __restrict__ W2, const float* __restrict__ b2,
                       const float* __restrict__ pg, const float* __restrict__ pb,
                       float* __restrict__ out) {
    int i = blockIdx.x, b = blockIdx.y, tid = threadIdx.x;  // 128 threads
    int l = (LL - 1) + i;
    float acc = b1[tid];
    const float* Hb = g_h + (size_t)b * DM * LTP + l;
    #pragma unroll 4
    for (int d = 0; d < DM; ++d) {
        float v = fmaf(Hb[(size_t)d * LTP] - g_mean[d], g_rstd[d] * pg[d], pb[d]);
        acc = fmaf(v, W1[d * 128 + tid], acc);
    }
    float sv = acc * sigm(acc);
    __shared__ float sh[128];
    sh[tid] = sv * W2[tid];
    __syncthreads();
    for (int o = 64; o; o >>= 1) {
        if (tid < o) sh[tid] += sh[tid + o];
        __syncthreads();
    }
    if (tid == 0) out[b * HH + i] = sh[0] + b2[0];
}

// ---------------- launch ----------------
extern "C" void kernel_launch(void* const* d_in, const int* in_sizes, int n_in,
                              void* d_out, int out_size) {
    const float* x_past   = (const float*)d_in[0];
    const float* noisy    = (const float*)d_in[1];
    const float* t        = (const float*)d_in[2];
    const float* x_future = (const float*)d_in[3];
    const float* stat     = (const float*)d_in[4];
    const float* freqs    = (const float*)d_in[5];
    const float* phases   = (const float*)d_in[6];
    const float* in_W     = (const float*)d_in[7];
    const float* in_b     = (const float*)d_in[8];
    const float* tm_W1    = (const float*)d_in[9];
    const float* tm_b1    = (const float*)d_in[10];
    const float* tm_W2    = (const float*)d_in[11];
    const float* tm_b2    = (const float*)d_in[12];
    const float* log_dt   = (const float*)d_in[13];
    const float* A_re     = (const float*)d_in[14];
    const float* A_im     = (const float*)d_in[15];
    const float* C_re     = (const float*)d_in[16];
    const float* C_im     = (const float*)d_in[17];
    const float* Dv       = (const float*)d_in[18];
    const float* out_W    = (const float*)d_in[19];
    const float* out_b    = (const float*)d_in[20];
    const float* bn_g     = (const float*)d_in[21];
    const float* bn_b     = (const float*)d_in[22];
    const float* hW1      = (const float*)d_in[23];
    const float* hb1      = (const float*)d_in[24];
    const float* hW2      = (const float*)d_in[25];
    const float* hb2      = (const float*)d_in[26];
    float* out = (float*)d_out;

    k_timemlp<<<BB, 256>>>(t, freqs, phases, tm_W1, tm_b1, tm_W2, tm_b2);
    k_inproj<<<dim3(65, DM / 8, BB), 256>>>(x_past, noisy, x_future, stat, in_W, in_b);

    for (int i = 0; i < NLAYERS; ++i) {
        const float* pg = (i == 0) ? bn_g : bn_g + (i - 1) * DM;
        const float* pb = (i == 0) ? bn_b : bn_b + (i - 1) * DM;
        k_scan<<<(BB * DM) / 8, 256>>>(log_dt + i * DM,
                                       A_re + (size_t)i * DM * DS, A_im + (size_t)i * DM * DS,
                                       C_re + (size_t)i * DM * DS, C_im + (size_t)i * DM * DS,
                                       Dv + i * DM, pg, pb, i > 0);
        k_gemm<<<dim3(17, 4, BB), 256>>>(out_W + (size_t)i * DM * 2 * DM,
                                         out_b + i * 2 * DM, pg, pb, i > 0);
        k_bnfin<<<DM, 128>>>();
    }
    k_head<<<dim3(HH, BB), 128>>>(hW1, hb1, hW2, hb2, bn_g + 3 * DM, bn_b + 3 * DM, out);
}

// round 6
// speedup vs baseline: 1.1806x; 1.1806x over previous
#include <cuda_runtime.h>
#include <cuda_bf16.h>
#include <math.h>

#define BB 32
#define LL 2048
#define HH 8
#define DMET 16
#define SDIM 27
#define DM 256
#define NLAYERS 4
#define DS 64
#define TE 256
#define LT 2055          // LL + HH - 1
#define LTP 2056         // padded row stride for g_h
#define LTT 2112         // 33*64 padded yT rows
#define FIN 44
#define NT 4224          // 33 l-tiles * 32 batches * 4 warp-quarters

typedef unsigned long long ull;
typedef unsigned int u32;

// ---------------- scratch (device globals; no allocation) ----------------
__device__ float g_h[(size_t)BB * DM * LTP];        // activations (pre-BN) [b][d][l]
__device__ u32 g_yh[(size_t)BB * LTT * 128];        // scan out, bf16-hi, [b][l][d/2] packed
__device__ u32 g_yl[(size_t)BB * LTT * 128];        // bf16-lo plane
__device__ u32 g_wh[512 * 128], g_wl[512 * 128];    // W^T split [e][d/2] packed
__device__ float g_tb[BB * DM];
__device__ float g_mean[DM], g_rstd[DM];
__device__ float g_bnp0[DM * NT], g_bnp1[DM * NT];

#define SCAN_SMEM (163968)   // 32*1152 f32 (sp) + 32*129 f32 (stage)
#define GEMM_SMEM (55296)    // 13824 u32

// ---------------- f32x2 packed math ----------------
__device__ __forceinline__ ull pk2(float a, float b) {
    ull r; asm("mov.b64 %0,{%1,%2};" : "=l"(r) : "f"(a), "f"(b)); return r;
}
__device__ __forceinline__ void up2(ull v, float& a, float& b) {
    asm("mov.b64 {%0,%1},%2;" : "=f"(a), "=f"(b) : "l"(v));
}
__device__ __forceinline__ ull f2fma(ull a, ull b, ull c) {
    ull d; asm("fma.rn.f32x2 %0,%1,%2,%3;" : "=l"(d) : "l"(a), "l"(b), "l"(c)); return d;
}
__device__ __forceinline__ ull f2mul(ull a, ull b) {
    ull d; asm("mul.rn.f32x2 %0,%1,%2;" : "=l"(d) : "l"(a), "l"(b)); return d;
}

// ---------------- helpers ----------------
__device__ __forceinline__ float sigm(float x) { return 1.f / (1.f + __expf(-x)); }
__device__ __forceinline__ float gelu_tanh(float v) {
    float v3 = v * v * v;
    float w = 1.5957691216057308f * fmaf(0.044715f, v3, v);
    return v * sigm(w);
}
__device__ __forceinline__ u32 bfsplit(float x, u32& lo) {
    __nv_bfloat16 h = __float2bfloat16(x);
    float r = x - __bfloat162float(h);
    __nv_bfloat16 l = __float2bfloat16(r);
    lo = (u32)__bfloat16_as_ushort(l);
    return (u32)__bfloat16_as_ushort(h);
}
__device__ __forceinline__ void mma16816(float* c, const u32* a, const u32* b) {
    asm volatile(
        "mma.sync.aligned.m16n8k16.row.col.f32.bf16.bf16.f32 "
        "{%0,%1,%2,%3},{%4,%5,%6,%7},{%8,%9},{%0,%1,%2,%3};"
        : "+f"(c[0]), "+f"(c[1]), "+f"(c[2]), "+f"(c[3])
        : "r"(a[0]), "r"(a[1]), "r"(a[2]), "r"(a[3]), "r"(b[0]), "r"(b[1]));
}

// ---------------- time MLP ----------------
__global__ void k_timemlp(const float* __restrict__ t, const float* __restrict__ freqs,
                          const float* __restrict__ phases,
                          const float* __restrict__ W1, const float* __restrict__ b1,
                          const float* __restrict__ W2, const float* __restrict__ b2) {
    int b = blockIdx.x, tid = threadIdx.x;
    __shared__ float tf[TE];
    __shared__ float hid[2 * TE];
    float tv = t[b];
    tf[tid] = cosf(fmaf(tv, freqs[tid], phases[tid])) * 1.41421356237309515f;
    __syncthreads();
    for (int j = tid; j < 2 * TE; j += 256) {
        float acc = b1[j];
        #pragma unroll 8
        for (int k = 0; k < TE; ++k) acc = fmaf(tf[k], W1[k * 512 + j], acc);
        hid[j] = acc * sigm(acc);
    }
    __syncthreads();
    float acc = b2[tid];
    #pragma unroll 8
    for (int k = 0; k < 2 * TE; ++k) acc = fmaf(hid[k], W2[k * 256 + tid], acc);
    g_tb[b * DM + tid] = acc;
}

// ---------------- input projection ----------------
__global__ void k_inproj(const float* __restrict__ xp, const float* __restrict__ noisy,
                         const float* __restrict__ xf, const float* __restrict__ sa,
                         const float* __restrict__ inW, const float* __restrict__ inb) {
    int b = blockIdx.z, dt = blockIdx.y, ltile = blockIdx.x;
    int tid = threadIdx.x;
    int ll = tid & 31, dl = tid >> 5;
    int l0 = ltile * 32, d0 = dt * 8;
    __shared__ float sf[32][45];
    __shared__ float sw[FIN][8];
    for (int i = tid; i < 32 * FIN; i += 256) {
        int li = i / FIN, f = i % FIN;
        int l = l0 + li;
        float v = 0.f;
        if (l < LT) {
            if (f < DMET)
                v = (l < LL) ? xp[((size_t)b * LL + l) * DMET + f]
                             : xf[((size_t)b * (HH - 1) + (l - LL)) * DMET + f];
            else if (f == DMET)
                v = (l >= LL - 1) ? noisy[b * HH + (l - (LL - 1))] : 0.f;
            else
                v = sa[b * SDIM + (f - DMET - 1)];
        }
        sf[li][f] = v;
    }
    for (int i = tid; i < FIN * 8; i += 256) {
        int f = i >> 3, c = i & 7;
        sw[f][c] = inW[f * DM + d0 + c];
    }
    __syncthreads();
    int l = l0 + ll, d = d0 + dl;
    float acc = inb[d];
    #pragma unroll
    for (int f = 0; f < FIN; ++f) acc = fmaf(sf[ll][f], sw[f][dl], acc);
    if (l >= LL - 1) acc += g_tb[b * DM + d];
    if (l < LT) g_h[((size_t)b * DM + d) * LTP + l] = acc;
}

// ---------------- weight transpose + bf16 split (per layer) ----------------
__global__ void k_wprep(const float* __restrict__ W) {
    int idx = blockIdx.x * 256 + threadIdx.x;   // 0..65535
    int e = idx & 511, kp = idx >> 9;           // kp 0..127
    float x0 = W[(2 * kp) * 512 + e];
    float x1 = W[(2 * kp + 1) * 512 + e];
    u32 lo0, lo1;
    u32 h0 = bfsplit(x0, lo0);
    u32 h1 = bfsplit(x1, lo1);
    g_wh[e * 128 + kp] = h0 | (h1 << 16);
    g_wl[e * 128 + kp] = lo0 | (lo1 << 16);
}

// ---- SSM scan: 1024 thr (32 warps = 32 d), inline disc, f32x2, transposed split out
extern "C" __global__ void __launch_bounds__(1024) k_scan(
        const float* __restrict__ log_dt, const float* __restrict__ Are,
        const float* __restrict__ Aim, const float* __restrict__ Cre,
        const float* __restrict__ Cim, const float* __restrict__ Dv,
        const float* __restrict__ pg, const float* __restrict__ pb, int apply_bn) {
    extern __shared__ float dyn[];
    int warp = threadIdx.x >> 5, lane = threadIdx.x & 31;
    float* sp = dyn + warp * 1152;          // [32 step][36] per warp
    float* stage = dyn + 32 * 1152;         // [32 d][129]
    int b = blockIdx.x >> 3, dbase = (blockIdx.x & 7) * 32;
    int d = dbase + warp;
    float mean = 0.f, scl = 1.f, bet = 0.f;
    if (apply_bn) { mean = g_mean[d]; scl = g_rstd[d] * pg[d]; bet = pb[d]; }
    // inline discretization
    float dt = __expf(log_dt[d]);
    float a0r, a0i, c0kr, c0ki, a1r, a1i, c1kr, c1ki;
    {
        int i0 = d * DS + lane, i1 = i0 + 32;
        #pragma unroll
        for (int s = 0; s < 2; ++s) {
            int ii = s ? i1 : i0;
            float ar_ = Are[ii], ai_ = Aim[ii];
            float xr = dt * ar_, xi = dt * ai_;
            float mag = expf(xr);
            float cs = cosf(xi), sn = sinf(xi);
            float A_r = mag * cs, A_i = mag * sn;
            float em = expm1f(xr);
            float er = fmaf(em, cs, cs - 1.f);
            float ei = A_i;
            float inv = 1.f / fmaf(ar_, ar_, ai_ * ai_);
            float qr = fmaf(er, ar_, ei * ai_) * inv;
            float qi = fmaf(ei, ar_, -er * ai_) * inv;
            float cr = Cre[ii], ci = Cim[ii];
            float kr = 2.f * fmaf(cr, qr, -ci * qi);
            float ki = 2.f * fmaf(cr, qi, ci * qr);
            if (s == 0) { a0r = A_r; a0i = A_i; c0kr = kr; c0ki = ki; }
            else        { a1r = A_r; a1i = A_i; c1kr = kr; c1ki = ki; }
        }
    }
    ull ar2  = pk2(a0r, a1r);
    ull ai2  = pk2(a0i, a1i);
    ull nai2 = pk2(-a0i, -a1i);
    ull cr2  = pk2(c0kr, c1kr);
    ull nci2 = pk2(-c0ki, -c1ki);
    ull sr2 = 0ull, si2 = 0ull;
    float Dd = Dv[d];
    const float* u = g_h + ((size_t)b * DM + d) * LTP;
    int dp = threadIdx.x & 15, lrel = threadIdx.x >> 4;   // transpose roles

    for (int c4 = 0; c4 < 16; ++c4) {
        for (int cc = 0; cc < 4; ++cc) {
            int l0 = c4 * 128 + cc * 32;
            float rv = u[l0 + lane];
            rv = fmaf(rv - mean, scl, bet);
            #pragma unroll
            for (int j = 0; j < 32; ++j) {
                float uv = __shfl_sync(0xffffffffu, rv, j);
                ull uv2 = pk2(uv, uv);
                ull t   = f2fma(nai2, si2, uv2);
                ull nsr = f2fma(ar2, sr2, t);
                ull nsi = f2fma(ai2, sr2, f2mul(ar2, si2));
                sr2 = nsr; si2 = nsi;
                ull pr = f2fma(cr2, sr2, f2mul(nci2, si2));
                float px, py; up2(pr, px, py);
                sp[j * 36 + lane] = px + py;     // [step][owner]
            }
            __syncwarp();
            float q0 = 0.f, q1 = 0.f, q2 = 0.f, q3 = 0.f;
            #pragma unroll
            for (int k4 = 0; k4 < 32; k4 += 4) {
                float4 q = *(const float4*)&sp[lane * 36 + k4];
                q0 += q.x; q1 += q.y; q2 += q.z; q3 += q.w;
            }
            float cs = (q0 + q1) + (q2 + q3);
            stage[warp * 129 + cc * 32 + lane] = gelu_tanh(fmaf(Dd, rv, cs));
            __syncwarp();
        }
        __syncthreads();
        #pragma unroll
        for (int p = 0; p < 2; ++p) {
            int l = lrel + p * 64;
            float v0 = stage[(2 * dp) * 129 + l];
            float v1 = stage[(2 * dp + 1) * 129 + l];
            u32 lo0, lo1;
            u32 h0 = bfsplit(v0, lo0);
            u32 h1 = bfsplit(v1, lo1);
            size_t row = ((size_t)b * LTT + c4 * 128 + l) * 128 + (dbase >> 1) + dp;
            g_yh[row] = h0 | (h1 << 16);
            g_yl[row] = lo0 | (lo1 << 16);
        }
        __syncthreads();
    }
    // tail: l = 2048..2054
    {
        float rv = 0.f;
        if (lane < 7) rv = fmaf(u[2048 + lane] - mean, scl, bet);
        #pragma unroll
        for (int j = 0; j < 7; ++j) {
            float uv = __shfl_sync(0xffffffffu, rv, j);
            ull uv2 = pk2(uv, uv);
            ull t   = f2fma(nai2, si2, uv2);
            ull nsr = f2fma(ar2, sr2, t);
            ull nsi = f2fma(ai2, sr2, f2mul(ar2, si2));
            sr2 = nsr; si2 = nsi;
            ull pr = f2fma(cr2, sr2, f2mul(nci2, si2));
            float px, py; up2(pr, px, py);
            sp[j * 36 + lane] = px + py;
        }
        __syncwarp();
        if (lane < 7) {
            float q0 = 0.f, q1 = 0.f, q2 = 0.f, q3 = 0.f;
            #pragma unroll
            for (int k4 = 0; k4 < 32; k4 += 4) {
                float4 q = *(const float4*)&sp[lane * 36 + k4];
                q0 += q.x; q1 += q.y; q2 += q.z; q3 += q.w;
            }
            float cs = (q0 + q1) + (q2 + q3);
            stage[warp * 129 + lane] = gelu_tanh(fmaf(Dd, rv, cs));
        }
        __syncthreads();
        if (lrel < 7) {
            float v0 = stage[(2 * dp) * 129 + lrel];
            float v1 = stage[(2 * dp + 1) * 129 + lrel];
            u32 lo0, lo1;
            u32 h0 = bfsplit(v0, lo0);
            u32 h1 = bfsplit(v1, lo1);
            size_t row = ((size_t)b * LTT + 2048 + lrel) * 128 + (dbase >> 1) + dp;
            g_yh[row] = h0 | (h1 << 16);
            g_yl[row] = lo0 | (lo1 << 16);
        }
        // zero padded rows 2055..2111 (this block's 16 d-pair columns)
        if (threadIdx.x < 912) {
            int l = 2055 + threadIdx.x / 16;
            int dp2 = threadIdx.x & 15;
            size_t row = ((size_t)b * LTT + l) * 128 + (dbase >> 1) + dp2;
            g_yh[row] = 0u;
            g_yl[row] = 0u;
        }
    }
}

// ---- out-proj GEMM: split-bf16 HMMA, 64e(x2 GLU halves) x 64l tile, fused epilogue --
extern "C" __global__ void __launch_bounds__(256) k_gemm(
        const float* __restrict__ ob, const float* __restrict__ pg,
        const float* __restrict__ pb, int apply_bn) {
    extern __shared__ u32 gsm[];
    // Ah: [0,4608)  Al: [4608,9216)  Bh: [9216,11520)  Bl: [11520,13824)
    const int bb = blockIdx.z, et = blockIdx.y, lt = blockIdx.x;
    const int e0 = et * 64, l0 = lt * 64;
    const int tid = threadIdx.x;
    const int wid = tid >> 5, lane = tid & 31;
    const int h = wid >> 2, wq = wid & 3;
    const int g = lane >> 2, t = lane & 3;
    float acc[4][2][4];
    #pragma unroll
    for (int mf = 0; mf < 4; ++mf)
        #pragma unroll
        for (int nf = 0; nf < 2; ++nf)
            #pragma unroll
            for (int r = 0; r < 4; ++r) acc[mf][nf][r] = 0.f;

    const int r_all = tid >> 3, j4 = (tid & 7) * 4;
    for (int kc = 0; kc < 4; ++kc) {
        const int kb2 = kc * 32;    // u32 column base
        __syncthreads();
        #pragma unroll
        for (int p = 0; p < 4; ++p) {
            int row = p * 32 + r_all;      // 0..127
            int hh = row >> 6, r = row & 63;
            int eg = e0 + (hh ? 256 : 0) + r;
            *(uint4*)&gsm[(hh * 64 + r) * 36 + j4] =
                *(const uint4*)&g_wh[(size_t)eg * 128 + kb2 + j4];
            *(uint4*)&gsm[4608 + (hh * 64 + r) * 36 + j4] =
                *(const uint4*)&g_wl[(size_t)eg * 128 + kb2 + j4];
        }
        #pragma unroll
        for (int p = 0; p < 2; ++p) {
            int lrow = p * 32 + r_all;     // 0..63
            size_t yrow = ((size_t)bb * LTT + l0 + lrow) * 128 + kb2 + j4;
            *(uint4*)&gsm[9216 + lrow * 36 + j4] = *(const uint4*)&g_yh[yrow];
            *(uint4*)&gsm[11520 + lrow * 36 + j4] = *(const uint4*)&g_yl[yrow];
        }
        __syncthreads();
        const u32* A_h = gsm + h * 2304;
        const u32* A_l = gsm + 4608 + h * 2304;
        #pragma unroll
        for (int ks = 0; ks < 4; ++ks) {
            u32 ah[4][4], al[4][4], bh[2][2], bl[2][2];
            #pragma unroll
            for (int mf = 0; mf < 4; ++mf) {
                int rb = (16 * mf + g) * 36 + ks * 8 + t;
                ah[mf][0] = A_h[rb];       ah[mf][1] = A_h[rb + 288];
                ah[mf][2] = A_h[rb + 4];   ah[mf][3] = A_h[rb + 292];
                al[mf][0] = A_l[rb];       al[mf][1] = A_l[rb + 288];
                al[mf][2] = A_l[rb + 4];   al[mf][3] = A_l[rb + 292];
            }
            #pragma unroll
            for (int nf = 0; nf < 2; ++nf) {
                int nr = (wq * 16 + nf * 8 + g) * 36 + ks * 8 + t;
                bh[nf][0] = gsm[9216 + nr];  bh[nf][1] = gsm[9216 + nr + 4];
                bl[nf][0] = gsm[11520 + nr]; bl[nf][1] = gsm[11520 + nr + 4];
            }
            #pragma unroll
            for (int mf = 0; mf < 4; ++mf)
                #pragma unroll
                for (int nf = 0; nf < 2; ++nf) {
                    mma16816(acc[mf][nf], ah[mf], bh[nf]);
                    mma16816(acc[mf][nf], ah[mf], bl[nf]);
                    mma16816(acc[mf][nf], al[mf], bh[nf]);
                }
        }
    }
    __syncthreads();
    float* zbuf = (float*)(gsm + 9216);     // [64][66], aliases B region
    if (h == 1) {
        #pragma unroll
        for (int mf = 0; mf < 4; ++mf)
            #pragma unroll
            for (int nf = 0; nf < 2; ++nf) {
                int lc = wq * 16 + nf * 8 + 2 * t;
                zbuf[(16 * mf + g) * 66 + lc]     = acc[mf][nf][0];
                zbuf[(16 * mf + g) * 66 + lc + 1] = acc[mf][nf][1];
                zbuf[(16 * mf + g + 8) * 66 + lc]     = acc[mf][nf][2];
                zbuf[(16 * mf + g + 8) * 66 + lc + 1] = acc[mf][nf][3];
            }
    }
    __syncthreads();
    if (h == 0) {
        float* Hb = g_h + (size_t)bb * DM * LTP;
        #pragma unroll
        for (int mf = 0; mf < 4; ++mf)
            #pragma unroll
            for (int rr = 0; rr < 2; ++rr) {
                int eloc = 16 * mf + g + 8 * rr;
                int d = e0 + eloc;
                float bz1 = ob[d], bz2 = ob[DM + d];
                float mn = 0.f, sc = 1.f, bt = 0.f;
                if (apply_bn) { mn = g_mean[d]; sc = g_rstd[d] * pg[d]; bt = pb[d]; }
                float* hrow = Hb + (size_t)d * LTP;
                float rsum = 0.f, rsq = 0.f;
                #pragma unroll
                for (int nf = 0; nf < 2; ++nf) {
                    int lc = wq * 16 + nf * 8 + 2 * t;
                    float z1a = acc[mf][nf][rr * 2 + 0] + bz1;
                    float z1b = acc[mf][nf][rr * 2 + 1] + bz1;
                    float z2a = zbuf[eloc * 66 + lc] + bz2;
                    float z2b = zbuf[eloc * 66 + lc + 1] + bz2;
                    float ga = z1a * sigm(z2a);
                    float gb = z1b * sigm(z2b);
                    int lg = l0 + lc;
                    if (lg < LT) {
                        float hn = fmaf(hrow[lg] - mn, sc, bt) + ga;
                        hrow[lg] = hn;
                        rsum += hn; rsq = fmaf(hn, hn, rsq);
                    }
                    if (lg + 1 < LT) {
                        float hn = fmaf(hrow[lg + 1] - mn, sc, bt) + gb;
                        hrow[lg + 1] = hn;
                        rsum += hn; rsq = fmaf(hn, hn, rsq);
                    }
                }
                rsum += __shfl_xor_sync(0xffffffffu, rsum, 1);
                rsum += __shfl_xor_sync(0xffffffffu, rsum, 2);
                rsq  += __shfl_xor_sync(0xffffffffu, rsq, 1);
                rsq  += __shfl_xor_sync(0xffffffffu, rsq, 2);
                if (t == 0) {
                    int slot = (lt * 32 + bb) * 4 + wq;
                    g_bnp0[d * NT + slot] = rsum;
                    g_bnp1[d * NT + slot] = rsq;
                }
            }
    }
}

// ---------------- BN finalize ----------------
__global__ void k_bnfin() {
    int d = blockIdx.x, tid = threadIdx.x;   // 256 threads
    float s = 0.f, s2 = 0.f;
    for (int i = tid; i < NT; i += 256) {
        s  += g_bnp0[d * NT + i];
        s2 += g_bnp1[d * NT + i];
    }
    __shared__ float sh1[256], sh2[256];
    sh1[tid] = s; sh2[tid] = s2;
    __syncthreads();
    for (int o = 128; o; o >>= 1) {
        if (tid < o) { sh1[tid] += sh1[tid + o]; sh2[tid] += sh2[tid + o]; }
        __syncthreads();
    }
    if (tid == 0) {
        float n = (float)(BB * LT);
        float mean = sh1[0] / n;
        float var = sh2[0] / n - mean * mean;
        g_mean[d] = mean;
        g_rstd[d] = rsqrtf(var + 1e-5f);
    }
}

// ---------------- head (applies final BN lazily) ----------------
__global__ void k_head(const float* __restrict__ W1, const float* __restrict__ b1,
                       const float* __restrict__ W2, const float* __restrict__ b2,
                       const float* __restrict__ pg, const float* __restrict__ pb,
                       float* __restrict__ out) {
    int i = blockIdx.x, b = blockIdx.y, tid = threadIdx.x;  // 128 threads
    int l = (LL - 1) + i;
    float acc = b1[tid];
    const float* Hb = g_h + (size_t)b * DM * LTP + l;
    #pragma unroll 4
    for (int d = 0; d < DM; ++d) {
        float v = fmaf(Hb[(size_t)d * LTP] - g_mean[d], g_rstd[d] * pg[d], pb[d]);
        acc = fmaf(v, W1[d * 128 + tid], acc);
    }
    float sv = acc * sigm(acc);
    __shared__ float sh[128];
    sh[tid] = sv * W2[tid];
    __syncthreads();
    for (int o = 64; o; o >>= 1) {
        if (tid < o) sh[tid] += sh[tid + o];
        __syncthreads();
    }
    if (tid == 0) out[b * HH + i] = sh[0] + b2[0];
}

// ---------------- launch ----------------
extern "C" void kernel_launch(void* const* d_in, const int* in_sizes, int n_in,
                              void* d_out, int out_size) {
    const float* x_past   = (const float*)d_in[0];
    const float* noisy    = (const float*)d_in[1];
    const float* t        = (const float*)d_in[2];
    const float* x_future = (const float*)d_in[3];
    const float* stat     = (const float*)d_in[4];
    const float* freqs    = (const float*)d_in[5];
    const float* phases   = (const float*)d_in[6];
    const float* in_W     = (const float*)d_in[7];
    const float* in_b     = (const float*)d_in[8];
    const float* tm_W1    = (const float*)d_in[9];
    const float* tm_b1    = (const float*)d_in[10];
    const float* tm_W2    = (const float*)d_in[11];
    const float* tm_b2    = (const float*)d_in[12];
    const float* log_dt   = (const float*)d_in[13];
    const float* A_re     = (const float*)d_in[14];
    const float* A_im     = (const float*)d_in[15];
    const float* C_re     = (const float*)d_in[16];
    const float* C_im     = (const float*)d_in[17];
    const float* Dv       = (const float*)d_in[18];
    const float* out_W    = (const float*)d_in[19];
    const float* out_b    = (const float*)d_in[20];
    const float* bn_g     = (const float*)d_in[21];
    const float* bn_b     = (const float*)d_in[22];
    const float* hW1      = (const float*)d_in[23];
    const float* hb1      = (const float*)d_in[24];
    const float* hW2      = (const float*)d_in[25];
    const float* hb2      = (const float*)d_in[26];
    float* out = (float*)d_out;

    cudaFuncSetAttribute(k_scan, cudaFuncAttributeMaxDynamicSharedMemorySize, SCAN_SMEM);
    cudaFuncSetAttribute(k_gemm, cudaFuncAttributeMaxDynamicSharedMemorySize, GEMM_SMEM);

    k_timemlp<<<BB, 256>>>(t, freqs, phases, tm_W1, tm_b1, tm_W2, tm_b2);
    k_inproj<<<dim3(65, DM / 8, BB), 256>>>(x_past, noisy, x_future, stat, in_W, in_b);

    for (int i = 0; i < NLAYERS; ++i) {
        const float* pg = (i == 0) ? bn_g : bn_g + (i - 1) * DM;
        const float* pb = (i == 0) ? bn_b : bn_b + (i - 1) * DM;
        k_wprep<<<256, 256>>>(out_W + (size_t)i * DM * 2 * DM);
        k_scan<<<256, 1024, SCAN_SMEM>>>(log_dt + i * DM,
                                         A_re + (size_t)i * DM * DS, A_im + (size_t)i * DM * DS,
                                         C_re + (size_t)i * DM * DS, C_im + (size_t)i * DM * DS,
                                         Dv + i * DM, pg, pb, i > 0);
        k_gemm<<<dim3(33, 4, BB), 256, GEMM_SMEM>>>(out_b + i * 2 * DM, pg, pb, i > 0);
        k_bnfin<<<DM, 256>>>();
    }
    k_head<<<dim3(HH, BB), 128>>>(hW1, hb1, hW2, hb2, bn_g + 3 * DM, bn_b + 3 * DM, out);
}